// round 14
// baseline (speedup 1.0000x reference)
#include <cuda_runtime.h>
#include <cstdint>

#define BATCH 2
#define SEQ 2048
#define DMODEL 1024
#define NHEADS 16
#define DK 64
#define NTOK (BATCH*SEQ)          /* 4096 */
#define NROWS (BATCH*NHEADS*SEQ)  /* 65536 */
#define NEGVAL (-1000000000.0f)

// ---------------- scratch (device globals: allocation-free) ----------------
__device__ float g_q[(size_t)BATCH*NHEADS*SEQ*DK];   // 16 MB  [B,H,S,dk]
__device__ float g_k[(size_t)BATCH*NHEADS*SEQ*DK];   // 16 MB
__device__ float g_v[(size_t)BATCH*NHEADS*SEQ*DK];   // 16 MB
__device__ float g_ctx[(size_t)NTOK*DMODEL];         // 16 MB  [B,S,D]
__device__ float2 g_ml[NROWS];                       // 512 KB (row max, row sum)

// ============================ bf16 split helpers ============================
__device__ __forceinline__ void split2(float x0, float x1,
                                       uint32_t& hp, uint32_t& lp) {
    asm("cvt.rn.bf16x2.f32 %0, %1, %2;" : "=r"(hp) : "f"(x1), "f"(x0));
    float h0 = __uint_as_float(hp << 16);
    float h1 = __uint_as_float(hp & 0xffff0000u);
    asm("cvt.rn.bf16x2.f32 %0, %1, %2;" : "=r"(lp) : "f"(x1 - h1), "f"(x0 - h0));
}
__device__ __forceinline__ void mma16(float* c, const uint32_t* a,
                                      const uint32_t* b) {
    asm volatile("mma.sync.aligned.m16n8k16.row.col.f32.bf16.bf16.f32 "
                 "{%0,%1,%2,%3}, {%4,%5,%6,%7}, {%8,%9}, {%0,%1,%2,%3};"
                 : "+f"(c[0]), "+f"(c[1]), "+f"(c[2]), "+f"(c[3])
                 : "r"(a[0]), "r"(a[1]), "r"(a[2]), "r"(a[3]),
                   "r"(b[0]), "r"(b[1]));
}

// ==================== bf16 3x GEMM core (k16, double-buffered) ==============
// C[128,128] = A[row0:+128, :] @ B[col0:+128, :]^T  (both [*,1024] f32 K-major)
// smem tiles: 128 rows x 8 words (BK=16 -> 8 bf16x2), row stride 12 words.
#define RS 12
#define TILE_W (128*RS)

struct GemmSmem {
    uint32_t Ah[TILE_W];
    uint32_t Al[TILE_W];
    uint32_t Bh[TILE_W];
    uint32_t Bl[TILE_W];
};

__device__ __forceinline__ void stage_gemm(
    const float* __restrict__ A, const float* __restrict__ B,
    int row0, int col0, int k0, GemmSmem* sm, int tid)
{
#pragma unroll
    for (int l = 0; l < 2; l++) {
        int idx = tid + l * 256;
        int r = idx >> 2;
        int c4 = (idx & 3) * 4;
        int w = (idx & 3) * 2;
        float4 x = *(const float4*)&A[(size_t)(row0 + r) * DMODEL + k0 + c4];
        uint32_t h0, l0, h1, l1;
        split2(x.x, x.y, h0, l0);
        split2(x.z, x.w, h1, l1);
        *(uint2*)&sm->Ah[r*RS + w] = make_uint2(h0, h1);
        *(uint2*)&sm->Al[r*RS + w] = make_uint2(l0, l1);
        float4 y = *(const float4*)&B[(size_t)(col0 + r) * DMODEL + k0 + c4];
        uint32_t j0, m0, j1, m1;
        split2(y.x, y.y, j0, m0);
        split2(y.z, y.w, j1, m1);
        *(uint2*)&sm->Bh[r*RS + w] = make_uint2(j0, j1);
        *(uint2*)&sm->Bl[r*RS + w] = make_uint2(m0, m1);
    }
}

__device__ __forceinline__ void gemm_bf16x3(
    const float* __restrict__ A, const float* __restrict__ B,
    int row0, int col0, GemmSmem* smarr, float acc[4][4][4])
{
    const int tid = threadIdx.x;
    const int wid = tid >> 5, lane = tid & 31;
    const int g = lane >> 2, tig = lane & 3;
    const int warp_m = wid & 1;
    const int warp_n = wid >> 1;
    const int rA = warp_m * 64;
    const int cB = warp_n * 32;

#pragma unroll
    for (int mt = 0; mt < 4; mt++)
#pragma unroll
        for (int nt = 0; nt < 4; nt++)
#pragma unroll
            for (int q = 0; q < 4; q++) acc[mt][nt][q] = 0.f;

    stage_gemm(A, B, row0, col0, 0, &smarr[0], tid);
    __syncthreads();

    for (int it = 0; it < DMODEL / 16; it++) {
        GemmSmem* cur = &smarr[it & 1];
        if (it + 1 < DMODEL / 16)
            stage_gemm(A, B, row0, col0, (it + 1) * 16, &smarr[(it + 1) & 1], tid);

        uint32_t bh[4][2], bl[4][2];
#pragma unroll
        for (int nt = 0; nt < 4; nt++) {
            int nr = cB + nt*8 + g;
            bh[nt][0] = cur->Bh[nr*RS + tig];
            bh[nt][1] = cur->Bh[nr*RS + 4 + tig];
            bl[nt][0] = cur->Bl[nr*RS + tig];
            bl[nt][1] = cur->Bl[nr*RS + 4 + tig];
        }
#pragma unroll
        for (int mt = 0; mt < 4; mt++) {
            int ar = rA + mt*16 + g;
            uint32_t ah[4], al[4];
            ah[0] = cur->Ah[ar*RS + tig];
            ah[1] = cur->Ah[(ar+8)*RS + tig];
            ah[2] = cur->Ah[ar*RS + 4 + tig];
            ah[3] = cur->Ah[(ar+8)*RS + 4 + tig];
            al[0] = cur->Al[ar*RS + tig];
            al[1] = cur->Al[(ar+8)*RS + tig];
            al[2] = cur->Al[ar*RS + 4 + tig];
            al[3] = cur->Al[(ar+8)*RS + 4 + tig];
#pragma unroll
            for (int nt = 0; nt < 4; nt++) {
                mma16(acc[mt][nt], ah, bh[nt]);
                mma16(acc[mt][nt], ah, bl[nt]);
                mma16(acc[mt][nt], al, bh[nt]);
            }
        }
        __syncthreads();
    }
}

// ============================================================================
// Fused QKV projections
// ============================================================================
__global__ __launch_bounds__(256, 2)
void k_projmma(const float* __restrict__ Qin, const float* __restrict__ Kin,
               const float* __restrict__ Vin,
               const float* __restrict__ Wq, const float* __restrict__ Wk,
               const float* __restrict__ Wv,
               const float* __restrict__ bq, const float* __restrict__ bk,
               const float* __restrict__ bv)
{
    __shared__ GemmSmem sm[2];
    const int z = blockIdx.z;
    const float* X = (z == 0) ? Qin : (z == 1) ? Kin : Vin;
    const float* W = (z == 0) ? Wq  : (z == 1) ? Wk  : Wv;
    const float* bias = (z == 0) ? bq : (z == 1) ? bk : bv;
    float* out = (z == 0) ? g_q : (z == 1) ? g_k : g_v;
    const int row0 = blockIdx.x * 128;
    const int col0 = blockIdx.y * 128;

    float acc[4][4][4];
    gemm_bf16x3(X, W, row0, col0, sm, acc);

    const int tid = threadIdx.x;
    const int wid = tid >> 5, lane = tid & 31;
    const int g = lane >> 2, tig = lane & 3;
    const int warp_m = wid & 1, warp_n = wid >> 1;

#pragma unroll
    for (int nt = 0; nt < 4; nt++) {
        int col = col0 + warp_n*32 + nt*8 + tig*2;
        float b0 = bias[col], b1 = bias[col + 1];
        int h = col >> 6, dd = col & 63;
#pragma unroll
        for (int mt = 0; mt < 4; mt++) {
            int token = row0 + warp_m*64 + mt*16 + g;
            int b = token >> 11, s = token & (SEQ - 1);
            float* base = &out[(((size_t)(b*NHEADS + h))*SEQ + s)*DK + dd];
            *(float2*)base = make_float2(acc[mt][nt][0] + b0, acc[mt][nt][1] + b1);
            float* base2 = base + (size_t)8 * DK;
            *(float2*)base2 = make_float2(acc[mt][nt][2] + b0, acc[mt][nt][3] + b1);
        }
    }
}

// ============================================================================
// Output GEMM + attn normalize, fused in one launch (grid-partitioned).
// ============================================================================
__global__ __launch_bounds__(256, 2)
void k_out_norm(const float* __restrict__ W, const float* __restrict__ bias,
                const float* __restrict__ resid, float* __restrict__ out,
                const float* __restrict__ scores_g, float* __restrict__ attn_g)
{
    __shared__ GemmSmem sm[2];
    const int tid = threadIdx.x;

    if (blockIdx.y >= 8) {
        // ---------------- normalize branch ----------------
        const int nid = (blockIdx.y - 8) * 32 + blockIdx.x;   // 0..511
        const int row0 = nid * 128;
        for (int r = 0; r < 128; r++) {
            const int row = row0 + r;
            float2 mlv = g_ml[row];
            const float m = mlv.x;
            const float inv = 1.0f / mlv.y;
            const float4* s4 = (const float4*)(scores_g + (size_t)row * SEQ);
            float4* a4 = (float4*)(attn_g + (size_t)row * SEQ);
#pragma unroll
            for (int l = 0; l < 2; l++) {
                int i = tid + l * 256;
                float4 s = s4[i];
                s.x = __expf(s.x - m) * inv;
                s.y = __expf(s.y - m) * inv;
                s.z = __expf(s.z - m) * inv;
                s.w = __expf(s.w - m) * inv;
                a4[i] = s;
            }
        }
        return;
    }

    // ---------------- GEMM branch ----------------
    const int row0 = blockIdx.x * 128;
    const int col0 = blockIdx.y * 128;

    float acc[4][4][4];
    gemm_bf16x3(g_ctx, W, row0, col0, sm, acc);

    const int wid = tid >> 5, lane = tid & 31;
    const int g = lane >> 2, tig = lane & 3;
    const int warp_m = wid & 1, warp_n = wid >> 1;

#pragma unroll
    for (int nt = 0; nt < 4; nt++) {
        int col = col0 + warp_n*32 + nt*8 + tig*2;
        float b0 = bias[col], b1 = bias[col + 1];
#pragma unroll
        for (int mt = 0; mt < 4; mt++) {
            int token = row0 + warp_m*64 + mt*16 + g;
            size_t gi = (size_t)token * DMODEL + col;
            float2 r0 = *(const float2*)&resid[gi];
            float2 r1 = *(const float2*)&resid[gi + 8*DMODEL];
            *(float2*)&out[gi] =
                make_float2(acc[mt][nt][0] + b0 + r0.x, acc[mt][nt][1] + b1 + r0.y);
            *(float2*)&out[gi + 8*DMODEL] =
                make_float2(acc[mt][nt][2] + b0 + r1.x, acc[mt][nt][3] + b1 + r1.y);
        }
    }
}

// ============================================================================
// Single-pass flash attention core, bf16x3 HMMA k16.
// CTA = 128 q-rows x one (b,h). 8 warps, 16 q-rows each. 32 k-tiles of 64.
// smem (uint32 words):
//   S_QLO [128][36] | S_KH [64][36] | S_KL | S_VH (V^T kpairs) | S_VL
// ============================================================================
#define KTILE 64
#define NKT (SEQ/KTILE)            /* 32 */
#define S_QLO 0
#define S_KH  4608
#define S_KL  6912
#define S_VH  9216
#define S_VL  11520
#define ATTN_WORDS 13824
#define ATTN_SMEM (ATTN_WORDS*4)   /* 55296 bytes */

__global__ __launch_bounds__(256, 2)
void k_attn_core(const unsigned char* __restrict__ mask,
                 float* __restrict__ scores_g)
{
    extern __shared__ uint32_t smu[];
    float* smf = (float*)smu;

    const int tid = threadIdx.x;
    const int wid = tid >> 5, lane = tid & 31;
    const int g = lane >> 2, tig = lane & 3;
    const int qb = blockIdx.x, bh = blockIdx.y;
    const int b = bh >> 4, h = bh & 15;
    const int qr0 = qb * 128;
    const float* qp = g_q + (size_t)bh * SEQ * DK;
    const float* kp = g_k + (size_t)bh * SEQ * DK;
    const float* vp = g_v + (size_t)bh * SEQ * DK;
    float* srow = scores_g + ((size_t)bh * SEQ + qr0) * SEQ;
    const int r0 = wid*16 + g, r1 = r0 + 8;

    // ---- stage Q raw (128x68 floats) into K/V region temporarily ----
#pragma unroll
    for (int l = 0; l < 8; l++) {
        int idx = tid + l * 256;
        int r = idx >> 4, c4 = (idx & 15) * 4;
        float4 q = *(const float4*)&qp[(size_t)(qr0 + r) * DK + c4];
        *(float4*)&smf[S_KH + r*68 + c4] = q;
    }
    __syncthreads();

    // ---- extract Q hi frags to regs, lo words to smem ----
    uint32_t aQh[8][2];
#pragma unroll
    for (int ks = 0; ks < 8; ks++) {
        int off = 8*ks + 2*tig;
        float2 q0 = *(const float2*)&smf[S_KH + r0*68 + off];
        float2 q1 = *(const float2*)&smf[S_KH + r1*68 + off];
        uint32_t ql0, ql1;
        split2(q0.x, q0.y, aQh[ks][0], ql0);
        split2(q1.x, q1.y, aQh[ks][1], ql1);
        smu[S_QLO + r0*36 + 4*ks + tig] = ql0;
        smu[S_QLO + r1*36 + 4*ks + tig] = ql1;
    }

    float mrow[2] = {-3.0e38f, -3.0e38f};
    float lrow[2] = {0.f, 0.f};
    float co[8][4];
#pragma unroll
    for (int nt = 0; nt < 8; nt++)
#pragma unroll
        for (int q = 0; q < 4; q++) co[nt][q] = 0.f;

    for (int kt = 0; kt < NKT; kt++) {
        __syncthreads();   // prev compute done (also guards Q-temp on kt=0)
        // ---- stage K tile: pairs along d ----
#pragma unroll
        for (int l = 0; l < 4; l++) {
            int idx = tid + l * 256;
            int r = idx >> 4, c4 = (idx & 15) * 4;
            int w = (idx & 15) * 2;
            float4 x = *(const float4*)&kp[(size_t)(kt*KTILE + r) * DK + c4];
            uint32_t h0, l0, h1, l1;
            split2(x.x, x.y, h0, l0);
            split2(x.z, x.w, h1, l1);
            *(uint2*)&smu[S_KH + r*36 + w] = make_uint2(h0, h1);
            *(uint2*)&smu[S_KL + r*36 + w] = make_uint2(l0, l1);
        }
        // ---- stage V^T: Vt[d][w] = pack(V[2w][d], V[2w+1][d]) ----
#pragma unroll
        for (int l = 0; l < 2; l++) {
            int idx = tid + l * 256;
            int w = idx & 31;
            int d4 = (idx >> 5) * 4;
            const float* v0 = &vp[(size_t)(kt*KTILE + 2*w) * DK + d4];
            float4 x0 = *(const float4*)v0;
            float4 x1 = *(const float4*)(v0 + DK);
            uint32_t hw, lw;
            split2(x0.x, x1.x, hw, lw);
            smu[S_VH + (d4+0)*36 + w] = hw;  smu[S_VL + (d4+0)*36 + w] = lw;
            split2(x0.y, x1.y, hw, lw);
            smu[S_VH + (d4+1)*36 + w] = hw;  smu[S_VL + (d4+1)*36 + w] = lw;
            split2(x0.z, x1.z, hw, lw);
            smu[S_VH + (d4+2)*36 + w] = hw;  smu[S_VL + (d4+2)*36 + w] = lw;
            split2(x0.w, x1.w, hw, lw);
            smu[S_VH + (d4+3)*36 + w] = hw;  smu[S_VL + (d4+3)*36 + w] = lw;
        }
        __syncthreads();

        // ---------------- scores = Q @ K^T (bf16 x3, k16) ----------------
        float acc[8][4];
#pragma unroll
        for (int nt = 0; nt < 8; nt++)
#pragma unroll
            for (int q = 0; q < 4; q++) acc[nt][q] = 0.f;

#pragma unroll
        for (int kk = 0; kk < 4; kk++) {
            uint32_t aqh[4] = {aQh[2*kk][0], aQh[2*kk][1],
                               aQh[2*kk+1][0], aQh[2*kk+1][1]};
            uint32_t aql[4];
            aql[0] = smu[S_QLO + r0*36 + 8*kk + tig];
            aql[1] = smu[S_QLO + r1*36 + 8*kk + tig];
            aql[2] = smu[S_QLO + r0*36 + 8*kk + 4 + tig];
            aql[3] = smu[S_QLO + r1*36 + 8*kk + 4 + tig];
#pragma unroll
            for (int nt = 0; nt < 8; nt++) {
                const int nr = nt*8 + g;
                uint32_t bhv[2], blv[2];
                bhv[0] = smu[S_KH + nr*36 + 8*kk + tig];
                bhv[1] = smu[S_KH + nr*36 + 8*kk + 4 + tig];
                blv[0] = smu[S_KL + nr*36 + 8*kk + tig];
                blv[1] = smu[S_KL + nr*36 + 8*kk + 4 + tig];
                mma16(acc[nt], aqh, bhv);
                mma16(acc[nt], aqh, blv);
                mma16(acc[nt], aql, bhv);
            }
        }

        // ---------------- scale + mask + store scores + stats ----------------
        const unsigned char* mk0 = mask + ((size_t)b*SEQ + qr0 + r0)*SEQ + kt*KTILE;
        const unsigned char* mk1 = mask + ((size_t)b*SEQ + qr0 + r1)*SEQ + kt*KTILE;
        float mn0 = mrow[0], mn1 = mrow[1];
#pragma unroll
        for (int nt = 0; nt < 8; nt++) {
            int c = nt*8 + tig*2;
            unsigned short m0 = *(const unsigned short*)(mk0 + c);
            unsigned short m1 = *(const unsigned short*)(mk1 + c);
            acc[nt][0] = (m0 & 0xff) ? NEGVAL : acc[nt][0] * 0.125f;
            acc[nt][1] = (m0 >> 8)  ? NEGVAL : acc[nt][1] * 0.125f;
            acc[nt][2] = (m1 & 0xff) ? NEGVAL : acc[nt][2] * 0.125f;
            acc[nt][3] = (m1 >> 8)  ? NEGVAL : acc[nt][3] * 0.125f;
            int cg = kt*KTILE + c;
            *(float2*)&srow[(size_t)r0 * SEQ + cg] = make_float2(acc[nt][0], acc[nt][1]);
            *(float2*)&srow[(size_t)r1 * SEQ + cg] = make_float2(acc[nt][2], acc[nt][3]);
            mn0 = fmaxf(mn0, fmaxf(acc[nt][0], acc[nt][1]));
            mn1 = fmaxf(mn1, fmaxf(acc[nt][2], acc[nt][3]));
        }
        mn0 = fmaxf(mn0, __shfl_xor_sync(0xffffffffu, mn0, 1));
        mn0 = fmaxf(mn0, __shfl_xor_sync(0xffffffffu, mn0, 2));
        mn1 = fmaxf(mn1, __shfl_xor_sync(0xffffffffu, mn1, 1));
        mn1 = fmaxf(mn1, __shfl_xor_sync(0xffffffffu, mn1, 2));

        const float sc0 = __expf(mrow[0] - mn0);
        const float sc1 = __expf(mrow[1] - mn1);
        float ts0 = 0.f, ts1 = 0.f;
#pragma unroll
        for (int nt = 0; nt < 8; nt++) {
            acc[nt][0] = __expf(acc[nt][0] - mn0);
            acc[nt][1] = __expf(acc[nt][1] - mn0);
            acc[nt][2] = __expf(acc[nt][2] - mn1);
            acc[nt][3] = __expf(acc[nt][3] - mn1);
            ts0 += acc[nt][0] + acc[nt][1];
            ts1 += acc[nt][2] + acc[nt][3];
            co[nt][0] *= sc0; co[nt][1] *= sc0;
            co[nt][2] *= sc1; co[nt][3] *= sc1;
        }
        ts0 += __shfl_xor_sync(0xffffffffu, ts0, 1);
        ts0 += __shfl_xor_sync(0xffffffffu, ts0, 2);
        ts1 += __shfl_xor_sync(0xffffffffu, ts1, 1);
        ts1 += __shfl_xor_sync(0xffffffffu, ts1, 2);
        lrow[0] = lrow[0] * sc0 + ts0;  mrow[0] = mn0;
        lrow[1] = lrow[1] * sc1 + ts1;  mrow[1] = mn1;

        // ---------------- ctx += E @ V (bf16 x3, k16) ----------------
#pragma unroll
        for (int kk = 0; kk < 4; kk++) {
            uint32_t a[4], al[4];
            split2(acc[2*kk][0],   acc[2*kk][1],   a[0], al[0]);
            split2(acc[2*kk][2],   acc[2*kk][3],   a[1], al[1]);
            split2(acc[2*kk+1][0], acc[2*kk+1][1], a[2], al[2]);
            split2(acc[2*kk+1][2], acc[2*kk+1][3], a[3], al[3]);
#pragma unroll
            for (int nt = 0; nt < 8; nt++) {
                const int d = nt*8 + g;
                uint32_t bhv[2], blv[2];
                bhv[0] = smu[S_VH + d*36 + 8*kk + tig];
                bhv[1] = smu[S_VH + d*36 + 8*kk + 4 + tig];
                blv[0] = smu[S_VL + d*36 + 8*kk + tig];
                blv[1] = smu[S_VL + d*36 + 8*kk + 4 + tig];
                mma16(co[nt], a, bhv);
                mma16(co[nt], a, blv);
                mma16(co[nt], al, bhv);
            }
        }
    }

    // ---- finalize: normalize ctx by 1/l, write ctx and (m,l) ----
    const float i0 = 1.0f / lrow[0];
    const float i1 = 1.0f / lrow[1];
#pragma unroll
    for (int nt = 0; nt < 8; nt++) {
        int d = nt*8 + tig*2;
        *(float2*)&g_ctx[((size_t)(b*SEQ) + qr0 + r0) * DMODEL + h*DK + d] =
            make_float2(co[nt][0] * i0, co[nt][1] * i0);
        *(float2*)&g_ctx[((size_t)(b*SEQ) + qr0 + r1) * DMODEL + h*DK + d] =
            make_float2(co[nt][2] * i1, co[nt][3] * i1);
    }
    if (tig == 0) {
        g_ml[bh*SEQ + qr0 + r0] = make_float2(mrow[0], lrow[0]);
        g_ml[bh*SEQ + qr0 + r1] = make_float2(mrow[1], lrow[1]);
    }
}

// ============================================================================
extern "C" void kernel_launch(void* const* d_in, const int* in_sizes, int n_in,
                              void* d_out, int out_size)
{
    const float* Q  = (const float*)d_in[0];
    const float* K  = (const float*)d_in[1];
    const float* V  = (const float*)d_in[2];
    const unsigned char* mask = (const unsigned char*)d_in[3];
    const float* Wq = (const float*)d_in[4];  const float* bq = (const float*)d_in[5];
    const float* Wk = (const float*)d_in[6];  const float* bk = (const float*)d_in[7];
    const float* Wv = (const float*)d_in[8];  const float* bv = (const float*)d_in[9];
    const float* Wo = (const float*)d_in[10]; const float* bo = (const float*)d_in[11];

    float* out    = (float*)d_out;
    float* attn   = out + (size_t)NTOK * DMODEL;
    float* scores = attn + (size_t)BATCH * NHEADS * SEQ * SEQ;

    cudaFuncSetAttribute(k_attn_core, cudaFuncAttributeMaxDynamicSharedMemorySize,
                         ATTN_SMEM);

    dim3 gp(NTOK / 128, DMODEL / 128, 3);       // 32 x 8 x 3
    k_projmma<<<gp, 256>>>(Q, K, V, Wq, Wk, Wv, bq, bk, bv);

    dim3 gf(SEQ / 128, BATCH * NHEADS);         // 16 x 32
    k_attn_core<<<gf, 256, ATTN_SMEM>>>(mask, scores);

    dim3 go(NTOK / 128, 8 + 16);                // y<8: gemm, y>=8: norm
    k_out_norm<<<go, 256>>>(Wo, bo, Q, out, scores, attn);
}

// round 15
// speedup vs baseline: 1.0061x; 1.0061x over previous
#include <cuda_runtime.h>
#include <cstdint>

#define BATCH 2
#define SEQ 2048
#define DMODEL 1024
#define NHEADS 16
#define DK 64
#define NTOK (BATCH*SEQ)          /* 4096 */
#define NROWS (BATCH*NHEADS*SEQ)  /* 65536 */
#define NEGVAL (-1000000000.0f)

// ---------------- scratch (device globals: allocation-free) ----------------
__device__ float g_q[(size_t)BATCH*NHEADS*SEQ*DK];   // 16 MB  [B,H,S,dk]
__device__ float g_k[(size_t)BATCH*NHEADS*SEQ*DK];   // 16 MB
__device__ float g_v[(size_t)BATCH*NHEADS*SEQ*DK];   // 16 MB
__device__ float g_ctx[(size_t)NTOK*DMODEL];         // 16 MB  [B,S,D]
__device__ float2 g_ml[NROWS];                       // 512 KB (row max, row sum)

// ============================ bf16 split helpers ============================
__device__ __forceinline__ void split2(float x0, float x1,
                                       uint32_t& hp, uint32_t& lp) {
    asm("cvt.rn.bf16x2.f32 %0, %1, %2;" : "=r"(hp) : "f"(x1), "f"(x0));
    float h0 = __uint_as_float(hp << 16);
    float h1 = __uint_as_float(hp & 0xffff0000u);
    asm("cvt.rn.bf16x2.f32 %0, %1, %2;" : "=r"(lp) : "f"(x1 - h1), "f"(x0 - h0));
}
__device__ __forceinline__ void mma16(float* c, const uint32_t* a,
                                      const uint32_t* b) {
    asm volatile("mma.sync.aligned.m16n8k16.row.col.f32.bf16.bf16.f32 "
                 "{%0,%1,%2,%3}, {%4,%5,%6,%7}, {%8,%9}, {%0,%1,%2,%3};"
                 : "+f"(c[0]), "+f"(c[1]), "+f"(c[2]), "+f"(c[3])
                 : "r"(a[0]), "r"(a[1]), "r"(a[2]), "r"(a[3]),
                   "r"(b[0]), "r"(b[1]));
}

// ==================== bf16 3x GEMM core (k16, double-buffered) ==============
// C[128,128] = A[row0:+128, :] @ B[col0:+128, :]^T  (both [*,1024] f32 K-major)
// smem tiles: 128 rows x 8 words (BK=16 -> 8 bf16x2), row stride 12 words.
#define RS 12
#define TILE_W (128*RS)

struct GemmSmem {
    uint32_t Ah[TILE_W];
    uint32_t Al[TILE_W];
    uint32_t Bh[TILE_W];
    uint32_t Bl[TILE_W];
};

__device__ __forceinline__ void stage_gemm(
    const float* __restrict__ A, const float* __restrict__ B,
    int row0, int col0, int k0, GemmSmem* sm, int tid)
{
#pragma unroll
    for (int l = 0; l < 2; l++) {
        int idx = tid + l * 256;
        int r = idx >> 2;
        int c4 = (idx & 3) * 4;
        int w = (idx & 3) * 2;
        float4 x = *(const float4*)&A[(size_t)(row0 + r) * DMODEL + k0 + c4];
        uint32_t h0, l0, h1, l1;
        split2(x.x, x.y, h0, l0);
        split2(x.z, x.w, h1, l1);
        *(uint2*)&sm->Ah[r*RS + w] = make_uint2(h0, h1);
        *(uint2*)&sm->Al[r*RS + w] = make_uint2(l0, l1);
        float4 y = *(const float4*)&B[(size_t)(col0 + r) * DMODEL + k0 + c4];
        uint32_t j0, m0, j1, m1;
        split2(y.x, y.y, j0, m0);
        split2(y.z, y.w, j1, m1);
        *(uint2*)&sm->Bh[r*RS + w] = make_uint2(j0, j1);
        *(uint2*)&sm->Bl[r*RS + w] = make_uint2(m0, m1);
    }
}

__device__ __forceinline__ void gemm_bf16x3(
    const float* __restrict__ A, const float* __restrict__ B,
    int row0, int col0, GemmSmem* smarr, float acc[4][4][4])
{
    const int tid = threadIdx.x;
    const int wid = tid >> 5, lane = tid & 31;
    const int g = lane >> 2, tig = lane & 3;
    const int warp_m = wid & 1;
    const int warp_n = wid >> 1;
    const int rA = warp_m * 64;
    const int cB = warp_n * 32;

#pragma unroll
    for (int mt = 0; mt < 4; mt++)
#pragma unroll
        for (int nt = 0; nt < 4; nt++)
#pragma unroll
            for (int q = 0; q < 4; q++) acc[mt][nt][q] = 0.f;

    stage_gemm(A, B, row0, col0, 0, &smarr[0], tid);
    __syncthreads();

    for (int it = 0; it < DMODEL / 16; it++) {
        GemmSmem* cur = &smarr[it & 1];
        if (it + 1 < DMODEL / 16)
            stage_gemm(A, B, row0, col0, (it + 1) * 16, &smarr[(it + 1) & 1], tid);

        uint32_t bh[4][2], bl[4][2];
#pragma unroll
        for (int nt = 0; nt < 4; nt++) {
            int nr = cB + nt*8 + g;
            bh[nt][0] = cur->Bh[nr*RS + tig];
            bh[nt][1] = cur->Bh[nr*RS + 4 + tig];
            bl[nt][0] = cur->Bl[nr*RS + tig];
            bl[nt][1] = cur->Bl[nr*RS + 4 + tig];
        }
#pragma unroll
        for (int mt = 0; mt < 4; mt++) {
            int ar = rA + mt*16 + g;
            uint32_t ah[4], al[4];
            ah[0] = cur->Ah[ar*RS + tig];
            ah[1] = cur->Ah[(ar+8)*RS + tig];
            ah[2] = cur->Ah[ar*RS + 4 + tig];
            ah[3] = cur->Ah[(ar+8)*RS + 4 + tig];
            al[0] = cur->Al[ar*RS + tig];
            al[1] = cur->Al[(ar+8)*RS + tig];
            al[2] = cur->Al[ar*RS + 4 + tig];
            al[3] = cur->Al[(ar+8)*RS + 4 + tig];
#pragma unroll
            for (int nt = 0; nt < 4; nt++) {
                mma16(acc[mt][nt], ah, bh[nt]);
                mma16(acc[mt][nt], ah, bl[nt]);
                mma16(acc[mt][nt], al, bh[nt]);
            }
        }
        __syncthreads();
    }
}

// ============================================================================
// Fused QKV projections
// ============================================================================
__global__ __launch_bounds__(256, 2)
void k_projmma(const float* __restrict__ Qin, const float* __restrict__ Kin,
               const float* __restrict__ Vin,
               const float* __restrict__ Wq, const float* __restrict__ Wk,
               const float* __restrict__ Wv,
               const float* __restrict__ bq, const float* __restrict__ bk,
               const float* __restrict__ bv)
{
    __shared__ GemmSmem sm[2];
    const int z = blockIdx.z;
    const float* X = (z == 0) ? Qin : (z == 1) ? Kin : Vin;
    const float* W = (z == 0) ? Wq  : (z == 1) ? Wk  : Wv;
    const float* bias = (z == 0) ? bq : (z == 1) ? bk : bv;
    float* out = (z == 0) ? g_q : (z == 1) ? g_k : g_v;
    const int row0 = blockIdx.x * 128;
    const int col0 = blockIdx.y * 128;

    float acc[4][4][4];
    gemm_bf16x3(X, W, row0, col0, sm, acc);

    const int tid = threadIdx.x;
    const int wid = tid >> 5, lane = tid & 31;
    const int g = lane >> 2, tig = lane & 3;
    const int warp_m = wid & 1, warp_n = wid >> 1;

#pragma unroll
    for (int nt = 0; nt < 4; nt++) {
        int col = col0 + warp_n*32 + nt*8 + tig*2;
        float b0 = bias[col], b1 = bias[col + 1];
        int h = col >> 6, dd = col & 63;
#pragma unroll
        for (int mt = 0; mt < 4; mt++) {
            int token = row0 + warp_m*64 + mt*16 + g;
            int b = token >> 11, s = token & (SEQ - 1);
            float* base = &out[(((size_t)(b*NHEADS + h))*SEQ + s)*DK + dd];
            *(float2*)base = make_float2(acc[mt][nt][0] + b0, acc[mt][nt][1] + b1);
            float* base2 = base + (size_t)8 * DK;
            *(float2*)base2 = make_float2(acc[mt][nt][2] + b0, acc[mt][nt][3] + b1);
        }
    }
}

// ============================================================================
// Output GEMM + attn normalize, fused in one launch (grid-partitioned).
// ============================================================================
__global__ __launch_bounds__(256, 2)
void k_out_norm(const float* __restrict__ W, const float* __restrict__ bias,
                const float* __restrict__ resid, float* __restrict__ out,
                const float* __restrict__ scores_g, float* __restrict__ attn_g)
{
    __shared__ GemmSmem sm[2];
    const int tid = threadIdx.x;

    if (blockIdx.y >= 8) {
        // ---------------- normalize branch ----------------
        const int nid = (blockIdx.y - 8) * 32 + blockIdx.x;   // 0..511
        const int row0 = nid * 128;
        for (int r = 0; r < 128; r++) {
            const int row = row0 + r;
            float2 mlv = g_ml[row];
            const float m = mlv.x;
            const float inv = 1.0f / mlv.y;
            const float4* s4 = (const float4*)(scores_g + (size_t)row * SEQ);
            float4* a4 = (float4*)(attn_g + (size_t)row * SEQ);
#pragma unroll
            for (int l = 0; l < 2; l++) {
                int i = tid + l * 256;
                float4 s = s4[i];
                s.x = __expf(s.x - m) * inv;
                s.y = __expf(s.y - m) * inv;
                s.z = __expf(s.z - m) * inv;
                s.w = __expf(s.w - m) * inv;
                a4[i] = s;
            }
        }
        return;
    }

    // ---------------- GEMM branch ----------------
    const int row0 = blockIdx.x * 128;
    const int col0 = blockIdx.y * 128;

    float acc[4][4][4];
    gemm_bf16x3(g_ctx, W, row0, col0, sm, acc);

    const int wid = tid >> 5, lane = tid & 31;
    const int g = lane >> 2, tig = lane & 3;
    const int warp_m = wid & 1, warp_n = wid >> 1;

#pragma unroll
    for (int nt = 0; nt < 4; nt++) {
        int col = col0 + warp_n*32 + nt*8 + tig*2;
        float b0 = bias[col], b1 = bias[col + 1];
#pragma unroll
        for (int mt = 0; mt < 4; mt++) {
            int token = row0 + warp_m*64 + mt*16 + g;
            size_t gi = (size_t)token * DMODEL + col;
            float2 r0 = *(const float2*)&resid[gi];
            float2 r1 = *(const float2*)&resid[gi + 8*DMODEL];
            *(float2*)&out[gi] =
                make_float2(acc[mt][nt][0] + b0 + r0.x, acc[mt][nt][1] + b1 + r0.y);
            *(float2*)&out[gi + 8*DMODEL] =
                make_float2(acc[mt][nt][2] + b0 + r1.x, acc[mt][nt][3] + b1 + r1.y);
        }
    }
}

// ============================================================================
// Single-pass flash attention core, bf16x3 HMMA k16.
// CTA = 128 q-rows x one (b,h). 8 warps, 16 q-rows each. 32 k-tiles of 64.
// smem (uint32 words):
//   S_QLO [128][36] | S_KH [64][36] | S_KL | S_VH (V^T kpairs) | S_VL
// ============================================================================
#define KTILE 64
#define NKT (SEQ/KTILE)            /* 32 */
#define S_QLO 0
#define S_KH  4608
#define S_KL  6912
#define S_VH  9216
#define S_VL  11520
#define ATTN_WORDS 13824
#define ATTN_SMEM (ATTN_WORDS*4)   /* 55296 bytes */

__global__ __launch_bounds__(256, 2)
void k_attn_core(const unsigned char* __restrict__ mask,
                 float* __restrict__ scores_g)
{
    extern __shared__ uint32_t smu[];
    float* smf = (float*)smu;

    const int tid = threadIdx.x;
    const int wid = tid >> 5, lane = tid & 31;
    const int g = lane >> 2, tig = lane & 3;
    const int qb = blockIdx.x, bh = blockIdx.y;
    const int b = bh >> 4, h = bh & 15;
    const int qr0 = qb * 128;
    const float* qp = g_q + (size_t)bh * SEQ * DK;
    const float* kp = g_k + (size_t)bh * SEQ * DK;
    const float* vp = g_v + (size_t)bh * SEQ * DK;
    float* srow = scores_g + ((size_t)bh * SEQ + qr0) * SEQ;
    const int r0 = wid*16 + g, r1 = r0 + 8;

    // ---- stage Q raw (128x68 floats) into K/V region temporarily ----
#pragma unroll
    for (int l = 0; l < 8; l++) {
        int idx = tid + l * 256;
        int r = idx >> 4, c4 = (idx & 15) * 4;
        float4 q = *(const float4*)&qp[(size_t)(qr0 + r) * DK + c4];
        *(float4*)&smf[S_KH + r*68 + c4] = q;
    }
    __syncthreads();

    // ---- extract Q hi frags to regs, lo words to smem ----
    uint32_t aQh[8][2];
#pragma unroll
    for (int ks = 0; ks < 8; ks++) {
        int off = 8*ks + 2*tig;
        float2 q0 = *(const float2*)&smf[S_KH + r0*68 + off];
        float2 q1 = *(const float2*)&smf[S_KH + r1*68 + off];
        uint32_t ql0, ql1;
        split2(q0.x, q0.y, aQh[ks][0], ql0);
        split2(q1.x, q1.y, aQh[ks][1], ql1);
        smu[S_QLO + r0*36 + 4*ks + tig] = ql0;
        smu[S_QLO + r1*36 + 4*ks + tig] = ql1;
    }

    float mrow[2] = {-3.0e38f, -3.0e38f};
    float lrow[2] = {0.f, 0.f};
    float co[8][4];
#pragma unroll
    for (int nt = 0; nt < 8; nt++)
#pragma unroll
        for (int q = 0; q < 4; q++) co[nt][q] = 0.f;

    for (int kt = 0; kt < NKT; kt++) {
        __syncthreads();   // prev compute done (also guards Q-temp on kt=0)
        // ---- stage K tile: pairs along d ----
#pragma unroll
        for (int l = 0; l < 4; l++) {
            int idx = tid + l * 256;
            int r = idx >> 4, c4 = (idx & 15) * 4;
            int w = (idx & 15) * 2;
            float4 x = *(const float4*)&kp[(size_t)(kt*KTILE + r) * DK + c4];
            uint32_t h0, l0, h1, l1;
            split2(x.x, x.y, h0, l0);
            split2(x.z, x.w, h1, l1);
            *(uint2*)&smu[S_KH + r*36 + w] = make_uint2(h0, h1);
            *(uint2*)&smu[S_KL + r*36 + w] = make_uint2(l0, l1);
        }
        // ---- stage V^T: Vt[d][w] = pack(V[2w][d], V[2w+1][d]) ----
#pragma unroll
        for (int l = 0; l < 2; l++) {
            int idx = tid + l * 256;
            int w = idx & 31;
            int d4 = (idx >> 5) * 4;
            const float* v0 = &vp[(size_t)(kt*KTILE + 2*w) * DK + d4];
            float4 x0 = *(const float4*)v0;
            float4 x1 = *(const float4*)(v0 + DK);
            uint32_t hw, lw;
            split2(x0.x, x1.x, hw, lw);
            smu[S_VH + (d4+0)*36 + w] = hw;  smu[S_VL + (d4+0)*36 + w] = lw;
            split2(x0.y, x1.y, hw, lw);
            smu[S_VH + (d4+1)*36 + w] = hw;  smu[S_VL + (d4+1)*36 + w] = lw;
            split2(x0.z, x1.z, hw, lw);
            smu[S_VH + (d4+2)*36 + w] = hw;  smu[S_VL + (d4+2)*36 + w] = lw;
            split2(x0.w, x1.w, hw, lw);
            smu[S_VH + (d4+3)*36 + w] = hw;  smu[S_VL + (d4+3)*36 + w] = lw;
        }
        __syncthreads();

        // ---------------- scores = Q @ K^T (bf16 x3, k16) ----------------
        float acc[8][4];
#pragma unroll
        for (int nt = 0; nt < 8; nt++)
#pragma unroll
            for (int q = 0; q < 4; q++) acc[nt][q] = 0.f;

#pragma unroll
        for (int kk = 0; kk < 4; kk++) {
            uint32_t aqh[4] = {aQh[2*kk][0], aQh[2*kk][1],
                               aQh[2*kk+1][0], aQh[2*kk+1][1]};
            uint32_t aql[4];
            aql[0] = smu[S_QLO + r0*36 + 8*kk + tig];
            aql[1] = smu[S_QLO + r1*36 + 8*kk + tig];
            aql[2] = smu[S_QLO + r0*36 + 8*kk + 4 + tig];
            aql[3] = smu[S_QLO + r1*36 + 8*kk + 4 + tig];
#pragma unroll
            for (int nt = 0; nt < 8; nt++) {
                const int nr = nt*8 + g;
                uint32_t bhv[2], blv[2];
                bhv[0] = smu[S_KH + nr*36 + 8*kk + tig];
                bhv[1] = smu[S_KH + nr*36 + 8*kk + 4 + tig];
                blv[0] = smu[S_KL + nr*36 + 8*kk + tig];
                blv[1] = smu[S_KL + nr*36 + 8*kk + 4 + tig];
                mma16(acc[nt], aqh, bhv);
                mma16(acc[nt], aqh, blv);
                mma16(acc[nt], aql, bhv);
            }
        }

        // ---------------- scale + mask + store scores + stats ----------------
        const unsigned char* mk0 = mask + ((size_t)b*SEQ + qr0 + r0)*SEQ + kt*KTILE;
        const unsigned char* mk1 = mask + ((size_t)b*SEQ + qr0 + r1)*SEQ + kt*KTILE;
        float mn0 = mrow[0], mn1 = mrow[1];
#pragma unroll
        for (int nt = 0; nt < 8; nt++) {
            int c = nt*8 + tig*2;
            unsigned short m0 = *(const unsigned short*)(mk0 + c);
            unsigned short m1 = *(const unsigned short*)(mk1 + c);
            acc[nt][0] = (m0 & 0xff) ? NEGVAL : acc[nt][0] * 0.125f;
            acc[nt][1] = (m0 >> 8)  ? NEGVAL : acc[nt][1] * 0.125f;
            acc[nt][2] = (m1 & 0xff) ? NEGVAL : acc[nt][2] * 0.125f;
            acc[nt][3] = (m1 >> 8)  ? NEGVAL : acc[nt][3] * 0.125f;
            int cg = kt*KTILE + c;
            *(float2*)&srow[(size_t)r0 * SEQ + cg] = make_float2(acc[nt][0], acc[nt][1]);
            *(float2*)&srow[(size_t)r1 * SEQ + cg] = make_float2(acc[nt][2], acc[nt][3]);
            mn0 = fmaxf(mn0, fmaxf(acc[nt][0], acc[nt][1]));
            mn1 = fmaxf(mn1, fmaxf(acc[nt][2], acc[nt][3]));
        }
        mn0 = fmaxf(mn0, __shfl_xor_sync(0xffffffffu, mn0, 1));
        mn0 = fmaxf(mn0, __shfl_xor_sync(0xffffffffu, mn0, 2));
        mn1 = fmaxf(mn1, __shfl_xor_sync(0xffffffffu, mn1, 1));
        mn1 = fmaxf(mn1, __shfl_xor_sync(0xffffffffu, mn1, 2));

        const float sc0 = __expf(mrow[0] - mn0);
        const float sc1 = __expf(mrow[1] - mn1);
        float ts0 = 0.f, ts1 = 0.f;
#pragma unroll
        for (int nt = 0; nt < 8; nt++) {
            acc[nt][0] = __expf(acc[nt][0] - mn0);
            acc[nt][1] = __expf(acc[nt][1] - mn0);
            acc[nt][2] = __expf(acc[nt][2] - mn1);
            acc[nt][3] = __expf(acc[nt][3] - mn1);
            ts0 += acc[nt][0] + acc[nt][1];
            ts1 += acc[nt][2] + acc[nt][3];
            co[nt][0] *= sc0; co[nt][1] *= sc0;
            co[nt][2] *= sc1; co[nt][3] *= sc1;
        }
        ts0 += __shfl_xor_sync(0xffffffffu, ts0, 1);
        ts0 += __shfl_xor_sync(0xffffffffu, ts0, 2);
        ts1 += __shfl_xor_sync(0xffffffffu, ts1, 1);
        ts1 += __shfl_xor_sync(0xffffffffu, ts1, 2);
        lrow[0] = lrow[0] * sc0 + ts0;  mrow[0] = mn0;
        lrow[1] = lrow[1] * sc1 + ts1;  mrow[1] = mn1;

        // ---------------- ctx += E @ V (bf16 x3, k16) ----------------
#pragma unroll
        for (int kk = 0; kk < 4; kk++) {
            uint32_t a[4], al[4];
            split2(acc[2*kk][0],   acc[2*kk][1],   a[0], al[0]);
            split2(acc[2*kk][2],   acc[2*kk][3],   a[1], al[1]);
            split2(acc[2*kk+1][0], acc[2*kk+1][1], a[2], al[2]);
            split2(acc[2*kk+1][2], acc[2*kk+1][3], a[3], al[3]);
#pragma unroll
            for (int nt = 0; nt < 8; nt++) {
                const int d = nt*8 + g;
                uint32_t bhv[2], blv[2];
                bhv[0] = smu[S_VH + d*36 + 8*kk + tig];
                bhv[1] = smu[S_VH + d*36 + 8*kk + 4 + tig];
                blv[0] = smu[S_VL + d*36 + 8*kk + tig];
                blv[1] = smu[S_VL + d*36 + 8*kk + 4 + tig];
                mma16(co[nt], a, bhv);
                mma16(co[nt], a, blv);
                mma16(co[nt], al, bhv);
            }
        }
    }

    // ---- finalize: normalize ctx by 1/l, write ctx and (m,l) ----
    const float i0 = 1.0f / lrow[0];
    const float i1 = 1.0f / lrow[1];
#pragma unroll
    for (int nt = 0; nt < 8; nt++) {
        int d = nt*8 + tig*2;
        *(float2*)&g_ctx[((size_t)(b*SEQ) + qr0 + r0) * DMODEL + h*DK + d] =
            make_float2(co[nt][0] * i0, co[nt][1] * i0);
        *(float2*)&g_ctx[((size_t)(b*SEQ) + qr0 + r1) * DMODEL + h*DK + d] =
            make_float2(co[nt][2] * i1, co[nt][3] * i1);
    }
    if (tig == 0) {
        g_ml[bh*SEQ + qr0 + r0] = make_float2(mrow[0], lrow[0]);
        g_ml[bh*SEQ + qr0 + r1] = make_float2(mrow[1], lrow[1]);
    }
}

// ============================================================================
extern "C" void kernel_launch(void* const* d_in, const int* in_sizes, int n_in,
                              void* d_out, int out_size)
{
    const float* Q  = (const float*)d_in[0];
    const float* K  = (const float*)d_in[1];
    const float* V  = (const float*)d_in[2];
    const unsigned char* mask = (const unsigned char*)d_in[3];
    const float* Wq = (const float*)d_in[4];  const float* bq = (const float*)d_in[5];
    const float* Wk = (const float*)d_in[6];  const float* bk = (const float*)d_in[7];
    const float* Wv = (const float*)d_in[8];  const float* bv = (const float*)d_in[9];
    const float* Wo = (const float*)d_in[10]; const float* bo = (const float*)d_in[11];

    float* out    = (float*)d_out;
    float* attn   = out + (size_t)NTOK * DMODEL;
    float* scores = attn + (size_t)BATCH * NHEADS * SEQ * SEQ;

    cudaFuncSetAttribute(k_attn_core, cudaFuncAttributeMaxDynamicSharedMemorySize,
                         ATTN_SMEM);

    dim3 gp(NTOK / 128, DMODEL / 128, 3);       // 32 x 8 x 3
    k_projmma<<<gp, 256>>>(Q, K, V, Wq, Wk, Wv, bq, bk, bv);

    dim3 gf(SEQ / 128, BATCH * NHEADS);         // 16 x 32
    k_attn_core<<<gf, 256, ATTN_SMEM>>>(mask, scores);

    dim3 go(NTOK / 128, 8 + 16);                // y<8: gemm, y>=8: norm
    k_out_norm<<<go, 256>>>(Wo, bo, Q, out, scores, attn);
}